// round 4
// baseline (speedup 1.0000x reference)
#include <cuda_runtime.h>
#include <cuda_bf16.h>

// TopDownProjector: for each column [b,c,y,x,:] (D=256 contiguous fp32),
// scan from depth D-1 downward for the first non-zero voxel.
//   out[0 .. N)   = height_field (depth index of hit, 0 if empty)
//   out[N .. 2N)  = seg_map (voxel value at hit, 0 if empty)
//
// Labels uniform [0,9): top float4 resolves a column with p = 1-(1/9)^4.
// 8 columns per thread: 8 independent LDG.128 (MLP=8), outputs written as
// two float4 per stream (fully coalesced). Rare unresolved columns fall
// back to a scalar descent.

static constexpr int D   = 256;
static constexpr int CPT = 8;     // columns per thread

__device__ __forceinline__ float2 resolve_col(const float* __restrict__ colp,
                                              float4 v) {
    int base = D - 4;
    for (;;) {
        if (v.w != 0.0f) return make_float2((float)(base + 3), v.w);
        if (v.z != 0.0f) return make_float2((float)(base + 2), v.z);
        if (v.y != 0.0f) return make_float2((float)(base + 1), v.y);
        if (v.x != 0.0f) return make_float2((float)(base + 0), v.x);
        base -= 4;
        if (base < 0) return make_float2(0.0f, 0.0f);
        v = *reinterpret_cast<const float4*>(colp + base);
    }
}

__global__ void __launch_bounds__(256)
topdown_kernel8(const float* __restrict__ volume,
                float4* __restrict__ height4,
                float4* __restrict__ seg4,
                int n_groups) {
    int g = blockIdx.x * blockDim.x + threadIdx.x;
    if (g >= n_groups) return;

    const float* base = volume + (size_t)g * CPT * D + (D - 4);

    // 8 independent top loads, issued back-to-back (MLP=8).
    float4 v[CPT];
    #pragma unroll
    for (int i = 0; i < CPT; ++i)
        v[i] = *reinterpret_cast<const float4*>(base + (size_t)i * D);

    float2 r[CPT];
    #pragma unroll
    for (int i = 0; i < CPT; ++i)
        r[i] = resolve_col(volume + ((size_t)g * CPT + i) * D, v[i]);

    // Coalesced 16B stores: 2 float4 per output stream.
    height4[g * 2 + 0] = make_float4(r[0].x, r[1].x, r[2].x, r[3].x);
    height4[g * 2 + 1] = make_float4(r[4].x, r[5].x, r[6].x, r[7].x);
    seg4[g * 2 + 0]    = make_float4(r[0].y, r[1].y, r[2].y, r[3].y);
    seg4[g * 2 + 1]    = make_float4(r[4].y, r[5].y, r[6].y, r[7].y);
}

// Scalar fallback for non-multiple-of-8 column counts (not hit for this shape).
__global__ void topdown_tail(const float* __restrict__ volume,
                             float* __restrict__ height,
                             float* __restrict__ seg,
                             int start, int n_cols) {
    int c = start + blockIdx.x * blockDim.x + threadIdx.x;
    if (c >= n_cols) return;
    const float* colp = volume + (size_t)c * D;
    float4 v = *reinterpret_cast<const float4*>(colp + (D - 4));
    float2 r = resolve_col(colp, v);
    height[c] = r.x;
    seg[c]    = r.y;
}

extern "C" void kernel_launch(void* const* d_in, const int* in_sizes, int n_in,
                              void* d_out, int out_size) {
    const float* volume = (const float*)d_in[0];
    float* out = (float*)d_out;

    int n_cols = in_sizes[0] / D;          // 524288 for [2,1,512,512,256]
    float* height = out;
    float* seg    = out + n_cols;

    int n_groups = n_cols / CPT;           // 65536
    int threads = 256;
    int blocks = (n_groups + threads - 1) / threads;   // 256 blocks
    topdown_kernel8<<<blocks, threads>>>(volume, (float4*)height,
                                         (float4*)seg, n_groups);

    int done = n_groups * CPT;
    if (done < n_cols) {
        int rem = n_cols - done;
        topdown_tail<<<(rem + 255) / 256, 256>>>(volume, height, seg,
                                                 done, n_cols);
    }
}